// round 11
// baseline (speedup 1.0000x reference)
#include <cuda_runtime.h>

#define D_MODEL 256
#define CH_TILE 8
#define POS_TILE 1024                   // 256 threads x float4
#define NBLK (148 * 6)                  // one resident wave at 6 CTAs/SM

// Collapsed conv per stream: zero-fill upsample + conv + strided gather reduces to
// a small FIR on the original samples (stream0: 1 tap, stream1: 3 taps, stream2: 5 taps).
template <int SID, bool GUARDED>
__device__ __forceinline__ void compute_item(
    const float* __restrict__ x, const float* __restrict__ W,
    const float* __restrict__ b, float* __restrict__ out,
    int l, int ML, int base, int ch0)
{
    const int p = base + threadIdx.x * 4;
    if (GUARDED && p >= ML) return;

    const bool live = !GUARDED || (p < l);

    // Window x[p-4 .. p+7] (12 floats, 3 float4), reused across CH_TILE channels.
    float xw[12];
    if (live) {
        #pragma unroll
        for (int j = 0; j < 3; j++) {
            const int bb = p - 4 + j * 4;
            float4 t;
            if (!GUARDED) {
                t = *reinterpret_cast<const float4*>(x + bb);
            } else if (bb >= 0 && bb + 4 <= l) {
                t = *reinterpret_cast<const float4*>(x + bb);
            } else {
                t.x = (bb     >= 0 && bb     < l) ? x[bb]     : 0.0f;
                t.y = (bb + 1 >= 0 && bb + 1 < l) ? x[bb + 1] : 0.0f;
                t.z = (bb + 2 >= 0 && bb + 2 < l) ? x[bb + 2] : 0.0f;
                t.w = (bb + 3 >= 0 && bb + 3 < l) ? x[bb + 3] : 0.0f;
            }
            xw[j * 4 + 0] = t.x; xw[j * 4 + 1] = t.y;
            xw[j * 4 + 2] = t.z; xw[j * 4 + 3] = t.w;
        }
    }

    #pragma unroll 1
    for (int c = 0; c < CH_TILE; c++) {
        const int ch = ch0 + c;
        float* rowOut = out + ((size_t)(SID * D_MODEL + ch)) * (size_t)ML + p;

        if (!live) {
            *reinterpret_cast<float4*>(rowOut) = make_float4(0.f, 0.f, 0.f, 0.f);
            continue;
        }

        const float bias = __ldg(&b[ch]);
        const float* Wc = W + ch * 5;
        float w0 = 0.f, w1 = 0.f, w2, w3 = 0.f, w4 = 0.f;
        w2 = __ldg(&Wc[2]);
        if (SID >= 1) { w0 = __ldg(&Wc[0]); w4 = __ldg(&Wc[4]); }
        if (SID == 2) { w1 = __ldg(&Wc[1]); w3 = __ldg(&Wc[3]); }

        float v[4];
        #pragma unroll
        for (int i = 0; i < 4; i++) {
            // xw index: x[p + k] == xw[4 + k]
            float val;
            if (SID == 0) {
                val = fmaf(w2, xw[4 + i], bias);
            } else if (SID == 1) {
                val = fmaf(w0, xw[3 + i],
                      fmaf(w2, xw[4 + i],
                      fmaf(w4, xw[5 + i], bias)));
            } else {
                val = fmaf(w0, xw[2 + i],
                      fmaf(w1, xw[3 + i],
                      fmaf(w2, xw[4 + i],
                      fmaf(w3, xw[5 + i],
                      fmaf(w4, xw[6 + i], bias)))));
            }
            v[i] = (!GUARDED || (p + i < l)) ? val : 0.0f;
        }
        // ML, p multiples of 4: p<ML implies p+4<=ML.
        *reinterpret_cast<float4*>(rowOut) = make_float4(v[0], v[1], v[2], v[3]);
    }
}

template <int SID>
__device__ __forceinline__ void zero_item(float* __restrict__ out,
                                          int ML, int base, int ch0)
{
    const int p = base + threadIdx.x * 4;
    if (p >= ML) return;
    const float4 z4 = make_float4(0.f, 0.f, 0.f, 0.f);
    #pragma unroll
    for (int c = 0; c < CH_TILE; c++) {
        float* rowOut = out + ((size_t)(SID * D_MODEL + ch0 + c)) * (size_t)ML + p;
        *reinterpret_cast<float4*>(rowOut) = z4;
    }
}

template <int SID>
__device__ __forceinline__ void run_item(
    const float* __restrict__ x, const float* __restrict__ W,
    const float* __restrict__ b, float* __restrict__ out,
    int l, int ML, int base, int ch0)
{
    if (base >= l) {
        zero_item<SID>(out, ML, base, ch0);
    } else if (base >= 4 && base + POS_TILE + 8 <= l && base + POS_TILE <= ML) {
        compute_item<SID, false>(x, W, b, out, l, ML, base, ch0);
    } else {
        compute_item<SID, true>(x, W, b, out, l, ML, base, ch0);
    }
}

__global__ __launch_bounds__(256, 6) void embed_x_kernel(
    const float* __restrict__ x0, const float* __restrict__ x1,
    const float* __restrict__ x2,
    const float* __restrict__ W, const float* __restrict__ b,
    float* __restrict__ out, int l0, int l1, int l2, int ML, int emit_s)
{
    const int nPosTiles = (ML + POS_TILE - 1) / POS_TILE;
    const int chTiles = D_MODEL / CH_TILE;
    const int itemsPerStream = chTiles * nPosTiles;
    const int nItems = 3 * itemsPerStream;

    for (int it = blockIdx.x; it < nItems; it += gridDim.x) {
        const int stream = it / itemsPerStream;
        const int r = it - stream * itemsPerStream;
        const int chT = r / nPosTiles;
        const int posT = r - chT * nPosTiles;
        const int base = posT * POS_TILE;
        const int ch0 = chT * CH_TILE;

        if (stream == 0)      run_item<0>(x0, W, b, out, l0, ML, base, ch0);
        else if (stream == 1) run_item<1>(x1, W, b, out, l1, ML, base, ch0);
        else                  run_item<2>(x2, W, b, out, l2, ML, base, ch0);

        // Fused S matrix: rows (first ML) then cols (next ML), ints stored
        // exactly as floats. Emitted by the (stream0, chTile0) item per range.
        if (emit_s && stream == 0 && chT == 0) {
            float* out_s = out + 3LL * D_MODEL * (long long)ML;
            #pragma unroll
            for (int i = 0; i < 4; i++) {
                const int j = base + threadIdx.x * 4 + i;
                if (j >= ML) break;
                int row, col;
                if (j < l0)                 { row = 0; col = j * 4; }
                else if (j < l0 + l1)       { row = 1; col = (j - l0) * 2; }
                else if (j < l0 + l1 + l2)  { row = 2; col = j - l0 - l1; }
                else                        { row = 0; col = 0; }
                out_s[j]      = (float)row;
                out_s[ML + j] = (float)col;
            }
        }
    }
}

extern "C" void kernel_launch(void* const* d_in, const int* in_sizes, int n_in,
                              void* d_out, int out_size)
{
    const float* x0 = (const float*)d_in[0];  // x_250
    const float* x1 = (const float*)d_in[1];  // x_500
    const float* x2 = (const float*)d_in[2];  // x_1000
    const float* W  = (const float*)d_in[3];  // [256,1,5]
    const float* b  = (const float*)d_in[4];  // [256]

    const int l0 = in_sizes[0];
    const int l1 = in_sizes[1];
    const int l2 = in_sizes[2];
    int ML = l0;
    if (l1 > ML) ML = l1;
    if (l2 > ML) ML = l2;

    float* out = (float*)d_out;

    const long long x_elems = 3LL * D_MODEL * (long long)ML;
    const int emit_s = ((long long)out_size >= x_elems + 2LL * ML) ? 1 : 0;

    const int nPosTiles = (ML + POS_TILE - 1) / POS_TILE;
    const int nItems = 3 * (D_MODEL / CH_TILE) * nPosTiles;
    int grid = NBLK < nItems ? NBLK : nItems;

    embed_x_kernel<<<grid, 256>>>(x0, x1, x2, W, b, out, l0, l1, l2, ML, emit_s);
}

// round 13
// speedup vs baseline: 1.0323x; 1.0323x over previous
#include <cuda_runtime.h>

#define D_MODEL 256
#define CH_TILE 16
#define QUADS 4                         // position-quads per thread per channel
#define WARP_POS (32 * 4 * QUADS)       // 512 positions per warp
#define BLOCK_WARPS 8
#define BLOCK_POS (WARP_POS * BLOCK_WARPS)  // 4096 positions per block

// Collapsed conv per stream: zero-fill upsample + conv + strided gather reduces to
// a small FIR on the original samples (stream0: 1 tap, stream1: 3 taps, stream2: 5 taps).
template <int SID, bool GUARDED>
__device__ __forceinline__ void run_compute(
    const float* __restrict__ x, const float* __restrict__ sW,
    const float* __restrict__ sb, float* __restrict__ out,
    int l, int ML)
{
    const int warp = threadIdx.x >> 5;
    const int lane = threadIdx.x & 31;
    const int warpBase = blockIdx.x * BLOCK_POS + warp * WARP_POS;

    // Input windows loaded ONCE per thread; reused across the 16-channel tile.
    // Window q covers x[pq-4 .. pq+7] (12 floats, 3 float4s).
    float xs[QUADS * 12];
    #pragma unroll
    for (int q = 0; q < QUADS; q++) {
        const int pq = warpBase + q * 128 + lane * 4;
        #pragma unroll
        for (int j = 0; j < 3; j++) {
            const int bb = pq - 4 + j * 4;
            float4 t;
            if (!GUARDED) {
                t = *reinterpret_cast<const float4*>(x + bb);
            } else if (bb >= 0 && bb + 4 <= l) {
                t = *reinterpret_cast<const float4*>(x + bb);
            } else {
                t.x = (bb     >= 0 && bb     < l) ? x[bb]     : 0.0f;
                t.y = (bb + 1 >= 0 && bb + 1 < l) ? x[bb + 1] : 0.0f;
                t.z = (bb + 2 >= 0 && bb + 2 < l) ? x[bb + 2] : 0.0f;
                t.w = (bb + 3 >= 0 && bb + 3 < l) ? x[bb + 3] : 0.0f;
            }
            xs[q * 12 + j * 4 + 0] = t.x;
            xs[q * 12 + j * 4 + 1] = t.y;
            xs[q * 12 + j * 4 + 2] = t.z;
            xs[q * 12 + j * 4 + 3] = t.w;
        }
    }

    const int ch0 = blockIdx.y * CH_TILE;
    #pragma unroll 1
    for (int c = 0; c < CH_TILE; c++) {
        const int ch = ch0 + c;
        const float bias = sb[ch];
        const float* Wc = sW + ch * 5;
        float w0 = 0.f, w1 = 0.f, w2, w3 = 0.f, w4 = 0.f;
        w2 = Wc[2];
        if (SID >= 1) { w0 = Wc[0]; w4 = Wc[4]; }
        if (SID == 2) { w1 = Wc[1]; w3 = Wc[3]; }

        float* rowOut = out + ((size_t)(SID * D_MODEL + ch)) * (size_t)ML;

        #pragma unroll
        for (int q = 0; q < QUADS; q++) {
            const int pq = warpBase + q * 128 + lane * 4;
            if (GUARDED && pq >= ML) continue;

            float v[4];
            #pragma unroll
            for (int i = 0; i < 4; i++) {
                // xs index: x[pq + k] == xs[q*12 + 4 + k]
                float val;
                if (SID == 0) {
                    val = fmaf(w2, xs[q * 12 + 4 + i], bias);
                } else if (SID == 1) {
                    val = fmaf(w0, xs[q * 12 + 3 + i],
                          fmaf(w2, xs[q * 12 + 4 + i],
                          fmaf(w4, xs[q * 12 + 5 + i], bias)));
                } else {
                    val = fmaf(w0, xs[q * 12 + 2 + i],
                          fmaf(w1, xs[q * 12 + 3 + i],
                          fmaf(w2, xs[q * 12 + 4 + i],
                          fmaf(w3, xs[q * 12 + 5 + i],
                          fmaf(w4, xs[q * 12 + 6 + i], bias)))));
                }
                v[i] = (!GUARDED || (pq + i < l)) ? val : 0.0f;
            }

            // BLOCK_POS and ML are multiples of 4: pq<ML implies pq+4<=ML.
            __stcs(reinterpret_cast<float4*>(rowOut + pq),
                   make_float4(v[0], v[1], v[2], v[3]));
        }
    }
}

template <int SID>
__device__ __forceinline__ void run_zero(float* __restrict__ out, int ML)
{
    const int warp = threadIdx.x >> 5;
    const int lane = threadIdx.x & 31;
    const int warpBase = blockIdx.x * BLOCK_POS + warp * WARP_POS;
    const int ch0 = blockIdx.y * CH_TILE;
    const float4 z4 = make_float4(0.f, 0.f, 0.f, 0.f);

    #pragma unroll 1
    for (int c = 0; c < CH_TILE; c++) {
        float* rowOut = out + ((size_t)(SID * D_MODEL + ch0 + c)) * (size_t)ML;
        #pragma unroll
        for (int q = 0; q < QUADS; q++) {
            const int pq = warpBase + q * 128 + lane * 4;
            if (pq < ML)
                __stcs(reinterpret_cast<float4*>(rowOut + pq), z4);
        }
    }
}

template <int SID>
__device__ __forceinline__ void run_stream(
    const float* __restrict__ x, const float* __restrict__ sW,
    const float* __restrict__ sb, float* __restrict__ out,
    int l, int ML)
{
    const int base = blockIdx.x * BLOCK_POS;
    if (base >= l) {
        run_zero<SID>(out, ML);
    } else if (base >= 4 && base + BLOCK_POS + 8 <= l) {
        run_compute<SID, false>(x, sW, sb, out, l, ML);
    } else {
        run_compute<SID, true>(x, sW, sb, out, l, ML);
    }
}

__global__ __launch_bounds__(256) void embed_x_kernel(
    const float* __restrict__ x0, const float* __restrict__ x1,
    const float* __restrict__ x2,
    const float* __restrict__ W, const float* __restrict__ b,
    float* __restrict__ out, int l0, int l1, int l2, int ML, int emit_s)
{
    // Stage all weights + biases in shared once per block: per-channel reads
    // become broadcast LDS instead of uniform LDGs stealing L1tex wavefronts
    // from the store stream.
    __shared__ float sW[D_MODEL * 5];
    __shared__ float sb[D_MODEL];
    for (int i = threadIdx.x; i < D_MODEL * 5; i += 256) sW[i] = W[i];
    for (int i = threadIdx.x; i < D_MODEL; i += 256)     sb[i] = b[i];
    __syncthreads();

    if (blockIdx.z == 0)      run_stream<0>(x0, sW, sb, out, l0, ML);
    else if (blockIdx.z == 1) run_stream<1>(x1, sW, sb, out, l1, ML);
    else                      run_stream<2>(x2, sW, sb, out, l2, ML);

    // Fused S matrix: rows (first ML) then cols (next ML), ints stored exactly
    // as floats. Handled by the (y==0, z==0) block slice for its position range.
    if (emit_s && blockIdx.y == 0 && blockIdx.z == 0) {
        float* out_s = out + 3LL * D_MODEL * (long long)ML;
        const int base = blockIdx.x * BLOCK_POS;
        #pragma unroll
        for (int k = 0; k < BLOCK_POS / 256; k++) {
            const int j = base + k * 256 + threadIdx.x;
            if (j >= ML) break;
            int row, col;
            if (j < l0)                 { row = 0; col = j * 4; }
            else if (j < l0 + l1)       { row = 1; col = (j - l0) * 2; }
            else if (j < l0 + l1 + l2)  { row = 2; col = j - l0 - l1; }
            else                        { row = 0; col = 0; }
            out_s[j]      = (float)row;
            out_s[ML + j] = (float)col;
        }
    }
}

extern "C" void kernel_launch(void* const* d_in, const int* in_sizes, int n_in,
                              void* d_out, int out_size)
{
    const float* x0 = (const float*)d_in[0];  // x_250
    const float* x1 = (const float*)d_in[1];  // x_500
    const float* x2 = (const float*)d_in[2];  // x_1000
    const float* W  = (const float*)d_in[3];  // [256,1,5]
    const float* b  = (const float*)d_in[4];  // [256]

    const int l0 = in_sizes[0];
    const int l1 = in_sizes[1];
    const int l2 = in_sizes[2];
    int ML = l0;
    if (l1 > ML) ML = l1;
    if (l2 > ML) ML = l2;

    float* out = (float*)d_out;

    const long long x_elems = 3LL * D_MODEL * (long long)ML;
    const int emit_s = ((long long)out_size >= x_elems + 2LL * ML) ? 1 : 0;

    dim3 block(256, 1, 1);
    dim3 grid((ML + BLOCK_POS - 1) / BLOCK_POS, D_MODEL / CH_TILE, 3);
    embed_x_kernel<<<grid, block>>>(x0, x1, x2, W, b, out, l0, l1, l2, ML, emit_s);
}